// round 1
// baseline (speedup 1.0000x reference)
#include <cuda_runtime.h>

#define BB 16
#define NN 1024
#define UU 64
#define MAXDEG 128
#define ALPHA 0.2f

// ---------------- scratch (device globals; no allocations) ----------------
__device__ int   g_cnt[NN];
__device__ int   g_nbr[NN * MAXDEG];
__device__ float g_h1 [BB * NN * 128];
__device__ float g_s1s[BB * NN];
__device__ float g_s1d[BB * NN];
__device__ float g_z  [BB * NN * UU];
__device__ float g_rs [BB * NN * UU];   // r * state
__device__ float g_h2 [BB * NN * UU];
__device__ float g_s2s[BB * NN];
__device__ float g_s2d[BB * NN];

// ---------------- K0: deterministic neighbor-list build ----------------
__global__ __launch_bounds__(256) void k_build(const float* __restrict__ adj) {
    int i = blockIdx.x;
    int t = threadIdx.x;
    __shared__ int cnts[256];

    // each thread scans 4 consecutive columns (vectorized)
    float4 v = *reinterpret_cast<const float4*>(adj + (size_t)i * NN + t * 4);
    int loc[4];
    int lc = 0;
    if (v.x > 0.f) loc[lc++] = t * 4 + 0;
    if (v.y > 0.f) loc[lc++] = t * 4 + 1;
    if (v.z > 0.f) loc[lc++] = t * 4 + 2;
    if (v.w > 0.f) loc[lc++] = t * 4 + 3;

    cnts[t] = lc;
    __syncthreads();
    // inclusive Hillis-Steele scan over 256
    #pragma unroll
    for (int d = 1; d < 256; d <<= 1) {
        int u = (t >= d) ? cnts[t - d] : 0;
        __syncthreads();
        cnts[t] += u;
        __syncthreads();
    }
    int start = cnts[t] - lc;
    #pragma unroll
    for (int q = 0; q < 4; q++) {
        if (q < lc) {
            int p = start + q;
            if (p < MAXDEG) g_nbr[i * MAXDEG + p] = loc[q];
        }
    }
    if (t == 255) g_cnt[i] = cnts[255] < MAXDEG ? cnts[255] : MAXDEG;
}

// ---------------- GEMM + attention-score kernel ----------------
// h[b,n,:] = concat(xa[b,n,:], xb[b,n,:]) @ W    (W: [128, FOUT])
// ss[b,n]  = h[b,n,:] . a[0:FOUT]
// sd[b,n]  = h[b,n,:] . a[FOUT:2*FOUT]
template <int FOUT>
__global__ __launch_bounds__(256) void k_gemm(const float* __restrict__ xa,
                                              const float* __restrict__ xb_ext,
                                              const float* __restrict__ W,
                                              const float* __restrict__ a) {
    const float* xb = (FOUT == 128) ? xb_ext : g_rs;
    float* h  = (FOUT == 128) ? g_h1  : g_h2;
    float* ss = (FOUT == 128) ? g_s1s : g_s2s;
    float* sd = (FOUT == 128) ? g_s1d : g_s2d;

    extern __shared__ float sm[];
    float* Wsm = sm;                                   // 128 * FOUT
    float (*Xs)[128] = (float(*)[128])(sm + 128 * FOUT); // 32 x 128

    const int CPL = FOUT / 32;  // cols per lane (4 or 2)
    int b = blockIdx.y, nc = blockIdx.x;
    int tid = threadIdx.x, lane = tid & 31, w = tid >> 5;

    // load W into smem (vectorized)
    for (int idx = tid * 4; idx < 128 * FOUT; idx += 256 * 4)
        *reinterpret_cast<float4*>(&Wsm[idx]) =
            *reinterpret_cast<const float4*>(&W[idx]);

    float av_s[4], av_d[4];
    #pragma unroll
    for (int c = 0; c < CPL; c++) {
        av_s[c] = a[lane * CPL + c];
        av_d[c] = a[FOUT + lane * CPL + c];
    }
    __syncthreads();

    for (int t = 0; t < 4; t++) {
        int row0 = nc * 128 + t * 32;
        if (t) __syncthreads();
        // load 32 rows of concatenated input
        for (int idx = tid; idx < 32 * 128; idx += 256) {
            int r = idx >> 7, f = idx & 127;
            int gi = (b * NN + row0 + r) * 64;
            Xs[r][f] = (f < 64) ? xa[gi + f] : xb[gi + f - 64];
        }
        __syncthreads();

        float acc[4][4];
        #pragma unroll
        for (int r = 0; r < 4; r++)
            #pragma unroll
            for (int c = 0; c < 4; c++) acc[r][c] = 0.f;

        int r0 = w * 4;
        #pragma unroll 4
        for (int f = 0; f < 128; f++) {
            float wv[4];
            #pragma unroll
            for (int c = 0; c < CPL; c++) wv[c] = Wsm[f * FOUT + lane * CPL + c];
            #pragma unroll
            for (int r = 0; r < 4; r++) {
                float x = Xs[r0 + r][f];
                #pragma unroll
                for (int c = 0; c < CPL; c++) acc[r][c] += x * wv[c];
            }
        }

        #pragma unroll
        for (int r = 0; r < 4; r++) {
            int gnode = row0 + r0 + r;
            size_t base = ((size_t)b * NN + gnode) * FOUT + lane * CPL;
            float ps = 0.f, pd = 0.f;
            #pragma unroll
            for (int c = 0; c < CPL; c++) {
                h[base + c] = acc[r][c];
                ps += acc[r][c] * av_s[c];
                pd += acc[r][c] * av_d[c];
            }
            #pragma unroll
            for (int off = 16; off; off >>= 1) {
                ps += __shfl_xor_sync(0xffffffffu, ps, off);
                pd += __shfl_xor_sync(0xffffffffu, pd, off);
            }
            if (lane == 0) {
                ss[b * NN + gnode] = ps;
                sd[b * NN + gnode] = pd;
            }
        }
    }
}

// ---------------- block reductions (128 threads = 4 warps) ----------------
__device__ __forceinline__ float blk_max(float v) {
    __shared__ float red[4];
    #pragma unroll
    for (int o = 16; o; o >>= 1) v = fmaxf(v, __shfl_xor_sync(0xffffffffu, v, o));
    if ((threadIdx.x & 31) == 0) red[threadIdx.x >> 5] = v;
    __syncthreads();
    float r = red[0];
    #pragma unroll
    for (int k = 1; k < 4; k++) r = fmaxf(r, red[k]);
    return r;
}
__device__ __forceinline__ float blk_sum(float v) {
    __shared__ float red[4];
    #pragma unroll
    for (int o = 16; o; o >>= 1) v += __shfl_xor_sync(0xffffffffu, v, o);
    if ((threadIdx.x & 31) == 0) red[threadIdx.x >> 5] = v;
    __syncthreads();
    float r = red[0];
    #pragma unroll
    for (int k = 1; k < 4; k++) r += red[k];
    return r;
}

// ---------------- K2: layer-1 attention + sigmoid gate ----------------
__global__ __launch_bounds__(128) void k_att1(const float* __restrict__ state) {
    int i = blockIdx.x, b = blockIdx.y;
    __shared__ float att[MAXDEG];
    __shared__ int   nb[MAXDEG];
    int tid = threadIdx.x;
    int deg = g_cnt[i];
    float si = g_s1s[b * NN + i];

    for (int k = tid; k < deg; k += 128) {
        int j = g_nbr[i * MAXDEG + k];
        nb[k] = j;
        float e = si + g_s1d[b * NN + j];
        att[k] = e > 0.f ? e : ALPHA * e;
    }
    __syncthreads();

    float m = -1e30f;
    for (int k = tid; k < deg; k += 128) m = fmaxf(m, att[k]);
    m = blk_max(m);

    float s = 0.f;
    for (int k = tid; k < deg; k += 128) {
        float v = __expf(att[k] - m);
        att[k] = v;
        s += v;
    }
    s = blk_sum(s);   // barrier inside also publishes att[] writes
    float inv = 1.f / s;

    float acc = 0.f;
    const float* h1b = g_h1 + (size_t)b * NN * 128;
    #pragma unroll 4
    for (int k = 0; k < deg; k++)
        acc += att[k] * h1b[(nb[k] << 7) + tid];
    acc *= inv;

    float gv = 1.f / (1.f + __expf(-acc));  // sigmoid
    int idx = (b * NN + i) * 64;
    if (tid < 64) g_rs[idx + tid] = gv * state[idx + tid];   // r * state
    else          g_z[idx + tid - 64] = gv;                  // z
}

// ---------------- K4: layer-2 attention + tanh + GRU blend ----------------
__global__ __launch_bounds__(128) void k_att2(const float* __restrict__ state,
                                              float* __restrict__ out) {
    int i = blockIdx.x, b = blockIdx.y;
    __shared__ float att[MAXDEG];
    __shared__ int   nb[MAXDEG];
    int tid = threadIdx.x;
    int deg = g_cnt[i];
    float si = g_s2s[b * NN + i];

    for (int k = tid; k < deg; k += 128) {
        int j = g_nbr[i * MAXDEG + k];
        nb[k] = j;
        float e = si + g_s2d[b * NN + j];
        att[k] = e > 0.f ? e : ALPHA * e;
    }
    __syncthreads();

    float m = -1e30f;
    for (int k = tid; k < deg; k += 128) m = fmaxf(m, att[k]);
    m = blk_max(m);

    float s = 0.f;
    for (int k = tid; k < deg; k += 128) {
        float v = __expf(att[k] - m);
        att[k] = v;
        s += v;
    }
    s = blk_sum(s);
    float inv = 1.f / s;

    if (tid < 64) {
        float acc = 0.f;
        const float* h2b = g_h2 + (size_t)b * NN * 64;
        #pragma unroll 4
        for (int k = 0; k < deg; k++)
            acc += att[k] * h2b[(nb[k] << 6) + tid];
        acc *= inv;

        float ht = tanhf(acc);
        int idx = (b * NN + i) * 64 + tid;
        float z  = g_z[idx];
        float st = state[idx];
        out[idx] = z * st + (1.f - z) * ht;
    }
}

// ---------------- launch ----------------
extern "C" void kernel_launch(void* const* d_in, const int* in_sizes, int n_in,
                              void* d_out, int out_size) {
    const float* X     = (const float*)d_in[0];
    const float* state = (const float*)d_in[1];
    const float* adj   = (const float*)d_in[2];
    const float* W1    = (const float*)d_in[3];
    const float* a1    = (const float*)d_in[4];
    const float* W2    = (const float*)d_in[5];
    const float* a2    = (const float*)d_in[6];
    float* out = (float*)d_out;

    const int SMEM_G1 = (128 * 128 + 32 * 128) * (int)sizeof(float); // 80 KB
    const int SMEM_G2 = (128 * 64  + 32 * 128) * (int)sizeof(float); // 48 KB
    cudaFuncSetAttribute(k_gemm<128>, cudaFuncAttributeMaxDynamicSharedMemorySize, SMEM_G1);
    cudaFuncSetAttribute(k_gemm<64>,  cudaFuncAttributeMaxDynamicSharedMemorySize, SMEM_G2);

    k_build<<<NN, 256>>>(adj);

    dim3 gg(8, BB);
    k_gemm<128><<<gg, 256, SMEM_G1>>>(X, state, W1, a1);

    dim3 ga(NN, BB);
    k_att1<<<ga, 128>>>(state);

    k_gemm<64><<<gg, 256, SMEM_G2>>>(X, state /*unused*/, W2, a2);

    k_att2<<<ga, 128>>>(state, out);
}

// round 3
// speedup vs baseline: 1.3233x; 1.3233x over previous
#include <cuda_runtime.h>
#include <cuda_fp16.h>

#define BB 16
#define NN 1024
#define UU 64
#define MAXDEG 128
#define ALPHA 0.2f

// ---------------- scratch (device globals; no allocations) ----------------
__device__ int     g_cnt[NN];
__device__ int     g_nbr[NN * MAXDEG];
__device__ __half2 g_h1h[BB * NN * 64];   // h1 as fp16, 128 cols = 64 half2
__device__ __half2 g_h2h[BB * NN * 32];   // h2 as fp16, 64 cols = 32 half2
__device__ float   g_s1s[BB * NN];
__device__ float   g_s1d[BB * NN];
__device__ float   g_z  [BB * NN * UU];
__device__ float   g_rs [BB * NN * UU];   // r * state
__device__ float   g_s2s[BB * NN];
__device__ float   g_s2d[BB * NN];

// ---------------- packed f32x2 helpers (SASS FFMA2) ----------------
typedef unsigned long long ull;
__device__ __forceinline__ void fma2(ull& d, ull a, ull b) {
    asm("fma.rn.f32x2 %0, %1, %2, %0;" : "+l"(d) : "l"(a), "l"(b));
}
__device__ __forceinline__ float2 unpack2(ull a) {
    float2 r;
    asm("mov.b64 {%0, %1}, %2;" : "=f"(r.x), "=f"(r.y) : "l"(a));
    return r;
}

// ---------------- K0: neighbor-list build via warp ballots ----------------
__global__ __launch_bounds__(256) void k_build(const float* __restrict__ adj) {
    int i = blockIdx.x, t = threadIdx.x, lane = t & 31, w = t >> 5;
    __shared__ int wtot[8];

    float4 v = *reinterpret_cast<const float4*>(adj + (size_t)i * NN + t * 4);
    unsigned f0 = v.x > 0.f, f1 = v.y > 0.f, f2 = v.z > 0.f, f3 = v.w > 0.f;
    unsigned m0 = __ballot_sync(~0u, f0), m1 = __ballot_sync(~0u, f1);
    unsigned m2 = __ballot_sync(~0u, f2), m3 = __ballot_sync(~0u, f3);
    unsigned lt = (1u << lane) - 1u;
    int pre = __popc(m0 & lt) + __popc(m1 & lt) + __popc(m2 & lt) + __popc(m3 & lt);
    if (lane == 0) wtot[w] = __popc(m0) + __popc(m1) + __popc(m2) + __popc(m3);
    __syncthreads();
    int base = 0;
    #pragma unroll
    for (int q = 0; q < 8; q++) base += (q < w) ? wtot[q] : 0;
    int p = base + pre;
    if (f0) { if (p < MAXDEG) g_nbr[i * MAXDEG + p] = t * 4 + 0; p++; }
    if (f1) { if (p < MAXDEG) g_nbr[i * MAXDEG + p] = t * 4 + 1; p++; }
    if (f2) { if (p < MAXDEG) g_nbr[i * MAXDEG + p] = t * 4 + 2; p++; }
    if (f3) { if (p < MAXDEG) g_nbr[i * MAXDEG + p] = t * 4 + 3; p++; }
    if (t == 255) {
        int tot = base + wtot[7];
        g_cnt[i] = tot < MAXDEG ? tot : MAXDEG;
    }
}

// ---------------- GEMM + attention-score kernel ----------------
// h16[b,n,:] = fp16( concat(xa, xb)[b,n,:] @ W )   (W: [128, FOUT])
// ss[b,n] = h . a[0:FOUT],  sd[b,n] = h . a[FOUT:2FOUT]   (fp32 scores)
template <int FOUT>
__global__ __launch_bounds__(256) void k_gemm(const float* __restrict__ xa,
                                              const float* __restrict__ xb_ext,
                                              const float* __restrict__ W,
                                              const float* __restrict__ a) {
    const float* xb = (FOUT == 128) ? xb_ext : g_rs;
    __half2* hh = (FOUT == 128) ? g_h1h : g_h2h;
    float* ss = (FOUT == 128) ? g_s1s : g_s2s;
    float* sd = (FOUT == 128) ? g_s1d : g_s2d;

    extern __shared__ float sm[];
    float2* Wp = (float2*)sm;                 // [64][FOUT] k-pair interleaved
    float*  Xs = sm + 2 * 64 * FOUT;          // [32][128]

    const int CPL = FOUT / 32;                // cols per lane: 4 or 2
    int b = blockIdx.y, nc = blockIdx.x;
    int tid = threadIdx.x, lane = tid & 31, w = tid >> 5;

    // W interleave: Wp[p*FOUT + c] = (W[2p][c], W[2p+1][c]) — coalesced over c
    for (int idx = tid; idx < 64 * FOUT; idx += 256) {
        int p = idx / FOUT, c = idx - p * FOUT;
        Wp[idx] = make_float2(W[(2 * p) * FOUT + c], W[(2 * p + 1) * FOUT + c]);
    }
    float av_s[4], av_d[4];
    #pragma unroll
    for (int c = 0; c < CPL; c++) {
        av_s[c] = a[lane * CPL + c];
        av_d[c] = a[FOUT + lane * CPL + c];
    }
    // X tile: 32 rows of concatenated [xa|xb]
    int row0 = nc * 32;
    for (int idx = tid * 4; idx < 32 * 128; idx += 1024) {
        int r = idx >> 7, f = idx & 127;
        const float* src = (f < 64) ? xa + ((size_t)b * NN + row0 + r) * 64 + f
                                    : xb + ((size_t)b * NN + row0 + r) * 64 + (f - 64);
        *reinterpret_cast<float4*>(Xs + idx) = *reinterpret_cast<const float4*>(src);
    }
    __syncthreads();

    ull acc[4][4];
    #pragma unroll
    for (int r = 0; r < 4; r++)
        #pragma unroll
        for (int c = 0; c < 4; c++) acc[r][c] = 0ull;

    int r0 = w * 4;
    const ull* Wp64 = (const ull*)Wp;
    const ull* Xp64 = (const ull*)Xs;

    #pragma unroll 4
    for (int p = 0; p < 64; p++) {
        ull wv[4];
        #pragma unroll
        for (int c = 0; c < CPL; c++) wv[c] = Wp64[p * FOUT + lane * CPL + c];
        #pragma unroll
        for (int r = 0; r < 4; r++) {
            ull x2 = Xp64[(r0 + r) * 64 + p];   // broadcast over warp
            #pragma unroll
            for (int c = 0; c < CPL; c++) fma2(acc[r][c], x2, wv[c]);
        }
    }

    #pragma unroll
    for (int r = 0; r < 4; r++) {
        int node = row0 + r0 + r;
        float outc[4];
        #pragma unroll
        for (int c = 0; c < CPL; c++) {
            float2 u = unpack2(acc[r][c]);
            outc[c] = u.x + u.y;
        }
        // fp16 store for the gather path
        size_t hbase = ((size_t)b * NN + node) * (FOUT / 2);
        if (CPL == 4) {
            uint2 pk;
            __half2 h0 = __floats2half2_rn(outc[0], outc[1]);
            __half2 h1 = __floats2half2_rn(outc[2], outc[3]);
            pk.x = *reinterpret_cast<unsigned*>(&h0);
            pk.y = *reinterpret_cast<unsigned*>(&h1);
            *reinterpret_cast<uint2*>(hh + hbase + lane * 2) = pk;
        } else {
            hh[hbase + lane] = __floats2half2_rn(outc[0], outc[1]);
        }
        float ps = 0.f, pd = 0.f;
        #pragma unroll
        for (int c = 0; c < CPL; c++) { ps += outc[c] * av_s[c]; pd += outc[c] * av_d[c]; }
        #pragma unroll
        for (int off = 16; off; off >>= 1) {
            ps += __shfl_xor_sync(0xffffffffu, ps, off);
            pd += __shfl_xor_sync(0xffffffffu, pd, off);
        }
        if (lane == 0) { ss[b * NN + node] = ps; sd[b * NN + node] = pd; }
    }
}

// ---------------- K2: layer-1 attention + sigmoid gate (warp per (b,i)) ----
__global__ __launch_bounds__(128) void k_att1(const float* __restrict__ state) {
    int w = threadIdx.x >> 5, lane = threadIdx.x & 31;
    int i = blockIdx.x * 4 + w, b = blockIdx.y;
    int deg = g_cnt[i];
    float si = g_s1s[b * NN + i];

    float ek[4]; int nk[4];
    #pragma unroll
    for (int q = 0; q < 4; q++) {
        int k = q * 32 + lane;
        bool val = k < deg;
        int j = val ? g_nbr[i * MAXDEG + k] : 0;
        nk[q] = j;
        float e = val ? si + g_s1d[b * NN + j] : -3e38f;
        ek[q] = e > 0.f ? e : ALPHA * e;
    }
    float m = fmaxf(fmaxf(ek[0], ek[1]), fmaxf(ek[2], ek[3]));
    #pragma unroll
    for (int o = 16; o; o >>= 1) m = fmaxf(m, __shfl_xor_sync(0xffffffffu, m, o));
    float s = 0.f;
    #pragma unroll
    for (int q = 0; q < 4; q++) {
        ek[q] = (q * 32 + lane < deg) ? __expf(ek[q] - m) : 0.f;
        s += ek[q];
    }
    #pragma unroll
    for (int o = 16; o; o >>= 1) s += __shfl_xor_sync(0xffffffffu, s, o);
    float inv = 1.f / s;

    float4 acc = {0.f, 0.f, 0.f, 0.f};
    const __half2* hb = g_h1h + (size_t)b * NN * 64;
    #pragma unroll
    for (int q = 0; q < 4; q++) {
        if (q * 32 >= deg) break;
        int kmax = deg - q * 32; if (kmax > 32) kmax = 32;
        #pragma unroll 4
        for (int l = 0; l < kmax; l++) {
            float wgt = __shfl_sync(0xffffffffu, ek[q], l);
            int   j   = __shfl_sync(0xffffffffu, nk[q], l);
            uint2 raw = *reinterpret_cast<const uint2*>(hb + (size_t)j * 64 + lane * 2);
            float2 fa = __half22float2(*reinterpret_cast<__half2*>(&raw.x));
            float2 fb = __half22float2(*reinterpret_cast<__half2*>(&raw.y));
            acc.x += wgt * fa.x; acc.y += wgt * fa.y;
            acc.z += wgt * fb.x; acc.w += wgt * fb.y;
        }
    }
    acc.x *= inv; acc.y *= inv; acc.z *= inv; acc.w *= inv;

    float4 gv;
    gv.x = 1.f / (1.f + __expf(-acc.x));
    gv.y = 1.f / (1.f + __expf(-acc.y));
    gv.z = 1.f / (1.f + __expf(-acc.z));
    gv.w = 1.f / (1.f + __expf(-acc.w));

    int idx = (b * NN + i) * 64;
    if (lane < 16) {     // cols 0..63 -> r: write r*state
        float4 st = *reinterpret_cast<const float4*>(state + idx + 4 * lane);
        float4 o = {gv.x * st.x, gv.y * st.y, gv.z * st.z, gv.w * st.w};
        *reinterpret_cast<float4*>(g_rs + idx + 4 * lane) = o;
    } else {             // cols 64..127 -> z
        *reinterpret_cast<float4*>(g_z + idx + 4 * lane - 64) = gv;
    }
}

// ---------------- K4: layer-2 attention + tanh + GRU blend ----------------
__global__ __launch_bounds__(128) void k_att2(const float* __restrict__ state,
                                              float* __restrict__ out) {
    int w = threadIdx.x >> 5, lane = threadIdx.x & 31;
    int i = blockIdx.x * 4 + w, b = blockIdx.y;
    int deg = g_cnt[i];
    float si = g_s2s[b * NN + i];

    float ek[4]; int nk[4];
    #pragma unroll
    for (int q = 0; q < 4; q++) {
        int k = q * 32 + lane;
        bool val = k < deg;
        int j = val ? g_nbr[i * MAXDEG + k] : 0;
        nk[q] = j;
        float e = val ? si + g_s2d[b * NN + j] : -3e38f;
        ek[q] = e > 0.f ? e : ALPHA * e;
    }
    float m = fmaxf(fmaxf(ek[0], ek[1]), fmaxf(ek[2], ek[3]));
    #pragma unroll
    for (int o = 16; o; o >>= 1) m = fmaxf(m, __shfl_xor_sync(0xffffffffu, m, o));
    float s = 0.f;
    #pragma unroll
    for (int q = 0; q < 4; q++) {
        ek[q] = (q * 32 + lane < deg) ? __expf(ek[q] - m) : 0.f;
        s += ek[q];
    }
    #pragma unroll
    for (int o = 16; o; o >>= 1) s += __shfl_xor_sync(0xffffffffu, s, o);
    float inv = 1.f / s;

    float2 acc = {0.f, 0.f};
    const __half2* hb = g_h2h + (size_t)b * NN * 32;
    #pragma unroll
    for (int q = 0; q < 4; q++) {
        if (q * 32 >= deg) break;
        int kmax = deg - q * 32; if (kmax > 32) kmax = 32;
        #pragma unroll 4
        for (int l = 0; l < kmax; l++) {
            float wgt = __shfl_sync(0xffffffffu, ek[q], l);
            int   j   = __shfl_sync(0xffffffffu, nk[q], l);
            unsigned raw = *reinterpret_cast<const unsigned*>(hb + (size_t)j * 32 + lane);
            float2 fa = __half22float2(*reinterpret_cast<__half2*>(&raw));
            acc.x += wgt * fa.x; acc.y += wgt * fa.y;
        }
    }
    acc.x *= inv; acc.y *= inv;

    int idx = (b * NN + i) * 64 + 2 * lane;
    float2 zz = *reinterpret_cast<const float2*>(g_z + idx);
    float2 st = *reinterpret_cast<const float2*>(state + idx);
    float2 o;
    o.x = zz.x * st.x + (1.f - zz.x) * tanhf(acc.x);
    o.y = zz.y * st.y + (1.f - zz.y) * tanhf(acc.y);
    *reinterpret_cast<float2*>(out + idx) = o;
}

// ---------------- launch ----------------
extern "C" void kernel_launch(void* const* d_in, const int* in_sizes, int n_in,
                              void* d_out, int out_size) {
    const float* X     = (const float*)d_in[0];
    const float* state = (const float*)d_in[1];
    const float* adj   = (const float*)d_in[2];
    const float* W1    = (const float*)d_in[3];
    const float* a1    = (const float*)d_in[4];
    const float* W2    = (const float*)d_in[5];
    const float* a2    = (const float*)d_in[6];
    float* out = (float*)d_out;

    const int SMEM_G1 = (2 * 64 * 128 + 32 * 128) * (int)sizeof(float); // 80 KB
    const int SMEM_G2 = (2 * 64 * 64  + 32 * 128) * (int)sizeof(float); // 48 KB
    static int inited = 0;
    if (!inited) {
        cudaFuncSetAttribute(k_gemm<128>, cudaFuncAttributeMaxDynamicSharedMemorySize, SMEM_G1);
        cudaFuncSetAttribute(k_gemm<64>,  cudaFuncAttributeMaxDynamicSharedMemorySize, SMEM_G2);
        inited = 1;
    }

    k_build<<<NN, 256>>>(adj);

    dim3 gg(NN / 32, BB);           // 512 blocks
    k_gemm<128><<<gg, 256, SMEM_G1>>>(X, state, W1, a1);

    dim3 ga(NN / 4, BB);            // warp per (b,i)
    k_att1<<<ga, 128>>>(state);

    k_gemm<64><<<gg, 256, SMEM_G2>>>(X, state /*unused*/, W2, a2);

    k_att2<<<ga, 128>>>(state, out);
}

// round 7
// speedup vs baseline: 2.0684x; 1.5630x over previous
#include <cuda_runtime.h>
#include <cuda_fp16.h>
#include <cstdint>

#define BB 16
#define NN 1024
#define UU 64
#define MAXDEG 128
#define ALPHA 0.2f

// ---------------- scratch (device globals; no allocations) ----------------
__device__ int     g_cnt[NN];
__device__ int     g_nbr[NN * MAXDEG];
__device__ __half2 g_h1h[BB * NN * 64];   // h1 fp16, 128 cols = 64 half2
__device__ __half2 g_h2h[BB * NN * 32];   // h2 fp16, 64 cols = 32 half2
__device__ float   g_s1s[BB * NN];
__device__ float   g_s1d[BB * NN];
__device__ float   g_z  [BB * NN * UU];
__device__ float   g_rs [BB * NN * UU];   // r * state
__device__ float   g_s2s[BB * NN];
__device__ float   g_s2d[BB * NN];

__device__ __forceinline__ uint32_t smem_u32(const void* p) {
    uint32_t a;
    asm("{ .reg .u64 t; cvta.to.shared.u64 t, %1; cvt.u32.u64 %0, t; }" : "=r"(a) : "l"(p));
    return a;
}
__device__ __forceinline__ void ldm_x4(uint32_t& r0, uint32_t& r1, uint32_t& r2, uint32_t& r3,
                                       uint32_t addr) {
    asm volatile("ldmatrix.sync.aligned.m8n8.x4.shared.b16 {%0,%1,%2,%3}, [%4];"
                 : "=r"(r0), "=r"(r1), "=r"(r2), "=r"(r3) : "r"(addr));
}
__device__ __forceinline__ void ldm_x4t(uint32_t& r0, uint32_t& r1, uint32_t& r2, uint32_t& r3,
                                        uint32_t addr) {
    asm volatile("ldmatrix.sync.aligned.m8n8.x4.trans.shared.b16 {%0,%1,%2,%3}, [%4];"
                 : "=r"(r0), "=r"(r1), "=r"(r2), "=r"(r3) : "r"(addr));
}
__device__ __forceinline__ void mma16816(float* c, uint32_t a0, uint32_t a1, uint32_t a2,
                                         uint32_t a3, uint32_t b0, uint32_t b1) {
    asm volatile(
        "mma.sync.aligned.m16n8k16.row.col.f32.f16.f16.f32 "
        "{%0,%1,%2,%3}, {%4,%5,%6,%7}, {%8,%9}, {%0,%1,%2,%3};"
        : "+f"(c[0]), "+f"(c[1]), "+f"(c[2]), "+f"(c[3])
        : "r"(a0), "r"(a1), "r"(a2), "r"(a3), "r"(b0), "r"(b1));
}

// ---------------- K0: neighbor-list build via warp ballots ----------------
__global__ __launch_bounds__(256) void k_build(const float* __restrict__ adj) {
    int i = blockIdx.x, t = threadIdx.x, lane = t & 31, w = t >> 5;
    __shared__ int wtot[8];

    float4 v = *reinterpret_cast<const float4*>(adj + (size_t)i * NN + t * 4);
    unsigned f0 = v.x > 0.f, f1 = v.y > 0.f, f2 = v.z > 0.f, f3 = v.w > 0.f;
    unsigned m0 = __ballot_sync(~0u, f0), m1 = __ballot_sync(~0u, f1);
    unsigned m2 = __ballot_sync(~0u, f2), m3 = __ballot_sync(~0u, f3);
    unsigned lt = (1u << lane) - 1u;
    int pre = __popc(m0 & lt) + __popc(m1 & lt) + __popc(m2 & lt) + __popc(m3 & lt);
    if (lane == 0) wtot[w] = __popc(m0) + __popc(m1) + __popc(m2) + __popc(m3);
    __syncthreads();
    int base = 0;
    #pragma unroll
    for (int q = 0; q < 8; q++) base += (q < w) ? wtot[q] : 0;
    int p = base + pre;
    if (f0) { if (p < MAXDEG) g_nbr[i * MAXDEG + p] = t * 4 + 0; p++; }
    if (f1) { if (p < MAXDEG) g_nbr[i * MAXDEG + p] = t * 4 + 1; p++; }
    if (f2) { if (p < MAXDEG) g_nbr[i * MAXDEG + p] = t * 4 + 2; p++; }
    if (f3) { if (p < MAXDEG) g_nbr[i * MAXDEG + p] = t * 4 + 3; p++; }
    if (t == 255) {
        int tot = base + wtot[7];
        g_cnt[i] = tot < MAXDEG ? tot : MAXDEG;
    }
}

// ---------------- HMMA GEMM + scores ----------------
// h[b,n,:] = fp16( concat(xa, xb)[b,n,:] @ W[128,FOUT] ),  ss/sd = h.a halves (fp32)
// Block: 256 thr / 8 warps; M=128 rows, N=FOUT, K=128; mma.m16n8k16 f16->f32.
template <int FOUT>
__global__ __launch_bounds__(256)
void k_mma(const float* __restrict__ xa, const float* __restrict__ xb_ext,
           const float* __restrict__ W, const float* __restrict__ a) {
    const float* xb = (FOUT == 128) ? xb_ext : g_rs;
    __half2* hh = (FOUT == 128) ? g_h1h : g_h2h;
    float* ss = (FOUT == 128) ? g_s1s : g_s2s;
    float* sd = (FOUT == 128) ? g_s1d : g_s2d;

    constexpr int AP = 136;        // padded halves/row (272B, ldmatrix conflict-free)
    constexpr int BP = FOUT + 8;   // padded halves/row
    constexpr int NT = FOUT / 8;   // n-tiles of 8

    extern __shared__ char sm[];
    __half* As = (__half*)sm;                       // [128][AP]
    __half* Bs = (__half*)(sm + 128 * AP * 2);      // [128][BP]
    float*  sA = (float*)(sm + 128 * AP * 2 + 128 * BP * 2);  // [2*FOUT]

    int tid = threadIdx.x, w = tid >> 5, lane = tid & 31;
    int nc = blockIdx.x, b = blockIdx.y;
    int row0 = nc * 128;

    // ---- stage A: 128 rows x 128 cols of concat(xa,xb), fp32->fp16 ----
    #pragma unroll
    for (int it = 0; it < 8; it++) {
        int idx = it * 256 + tid;          // 2048 chunks of 8 halves
        int row = idx >> 4;
        int col0 = (idx & 15) * 8;
        const float* src = (col0 < 64)
            ? xa + ((size_t)b * NN + row0 + row) * 64 + col0
            : xb + ((size_t)b * NN + row0 + row) * 64 + (col0 - 64);
        float4 f0 = *reinterpret_cast<const float4*>(src);
        float4 f1 = *reinterpret_cast<const float4*>(src + 4);
        __half2 h0 = __floats2half2_rn(f0.x, f0.y);
        __half2 h1 = __floats2half2_rn(f0.z, f0.w);
        __half2 h2 = __floats2half2_rn(f1.x, f1.y);
        __half2 h3 = __floats2half2_rn(f1.z, f1.w);
        uint4 pk;
        pk.x = *reinterpret_cast<unsigned*>(&h0);
        pk.y = *reinterpret_cast<unsigned*>(&h1);
        pk.z = *reinterpret_cast<unsigned*>(&h2);
        pk.w = *reinterpret_cast<unsigned*>(&h3);
        *reinterpret_cast<uint4*>(As + row * AP + col0) = pk;
    }
    // ---- stage B = W as-is: [128][FOUT] fp32 -> fp16 padded ----
    #pragma unroll
    for (int it = 0; it < FOUT / 16; it++) {       // 128*FOUT/8 / 256 iters
        int idx = it * 256 + tid;
        int k = idx / (FOUT / 8);
        int n0 = (idx - k * (FOUT / 8)) * 8;
        float4 f0 = *reinterpret_cast<const float4*>(W + (size_t)k * FOUT + n0);
        float4 f1 = *reinterpret_cast<const float4*>(W + (size_t)k * FOUT + n0 + 4);
        __half2 h0 = __floats2half2_rn(f0.x, f0.y);
        __half2 h1 = __floats2half2_rn(f0.z, f0.w);
        __half2 h2 = __floats2half2_rn(f1.x, f1.y);
        __half2 h3 = __floats2half2_rn(f1.z, f1.w);
        uint4 pk;
        pk.x = *reinterpret_cast<unsigned*>(&h0);
        pk.y = *reinterpret_cast<unsigned*>(&h1);
        pk.z = *reinterpret_cast<unsigned*>(&h2);
        pk.w = *reinterpret_cast<unsigned*>(&h3);
        *reinterpret_cast<uint4*>(Bs + k * BP + n0) = pk;
    }
    for (int c = tid; c < 2 * FOUT; c += 256) sA[c] = a[c];
    __syncthreads();

    // ---- mainloop ----
    float acc[NT][4];
    #pragma unroll
    for (int j = 0; j < NT; j++)
        #pragma unroll
        for (int q = 0; q < 4; q++) acc[j][q] = 0.f;

    uint32_t a_base = smem_u32(As + (w * 16 + (lane & 15)) * AP + ((lane >> 4) * 8));
    uint32_t b_base = smem_u32(Bs + (lane & 15) * BP + ((lane >> 4) * 8));

    #pragma unroll
    for (int kk = 0; kk < 8; kk++) {
        uint32_t a0, a1, a2, a3;
        ldm_x4(a0, a1, a2, a3, a_base + kk * 32);
        #pragma unroll
        for (int j = 0; j < NT / 2; j++) {
            uint32_t b0, b1, b2, b3;
            ldm_x4t(b0, b1, b2, b3, b_base + kk * (16 * BP * 2) + j * 32);
            mma16816(acc[2 * j],     a0, a1, a2, a3, b0, b1);
            mma16816(acc[2 * j + 1], a0, a1, a2, a3, b2, b3);
        }
    }

    // ---- epilogue: lane holds rows (g, g+8) of warp slab, cols 2q,2q+1 per n-tile ----
    int q = lane & 3, g = lane >> 2;
    int nodeA = row0 + w * 16 + g;
    int nodeB = nodeA + 8;
    size_t sbA = (size_t)b * NN + nodeA;
    size_t sbB = (size_t)b * NN + nodeB;
    __half2* hrA = hh + sbA * (FOUT / 2);
    __half2* hrB = hh + sbB * (FOUT / 2);

    float ps0 = 0.f, pd0 = 0.f, ps1 = 0.f, pd1 = 0.f;
    #pragma unroll
    for (int j = 0; j < NT; j++) {
        int c = j * 8 + 2 * q;
        ps0 += acc[j][0] * sA[c] + acc[j][1] * sA[c + 1];
        pd0 += acc[j][0] * sA[FOUT + c] + acc[j][1] * sA[FOUT + c + 1];
        ps1 += acc[j][2] * sA[c] + acc[j][3] * sA[c + 1];
        pd1 += acc[j][2] * sA[FOUT + c] + acc[j][3] * sA[FOUT + c + 1];
        hrA[c >> 1] = __floats2half2_rn(acc[j][0], acc[j][1]);
        hrB[c >> 1] = __floats2half2_rn(acc[j][2], acc[j][3]);
    }
    #pragma unroll
    for (int o = 1; o <= 2; o <<= 1) {
        ps0 += __shfl_xor_sync(0xffffffffu, ps0, o);
        pd0 += __shfl_xor_sync(0xffffffffu, pd0, o);
        ps1 += __shfl_xor_sync(0xffffffffu, ps1, o);
        pd1 += __shfl_xor_sync(0xffffffffu, pd1, o);
    }
    if (q == 0) {
        ss[sbA] = ps0; sd[sbA] = pd0;
        ss[sbB] = ps1; sd[sbB] = pd1;
    }
}

// ---------------- K2: layer-1 attention + sigmoid gate (warp per (b,i)) ----
__global__ __launch_bounds__(128) void k_att1(const float* __restrict__ state) {
    int w = threadIdx.x >> 5, lane = threadIdx.x & 31;
    int i = blockIdx.x * 4 + w, b = blockIdx.y;
    int deg = g_cnt[i];
    float si = g_s1s[b * NN + i];

    float ek[4]; int nk[4];
    #pragma unroll
    for (int q = 0; q < 4; q++) {
        int k = q * 32 + lane;
        bool val = k < deg;
        int j = val ? g_nbr[i * MAXDEG + k] : 0;
        nk[q] = j;
        float e = val ? si + g_s1d[b * NN + j] : -3e38f;
        ek[q] = e > 0.f ? e : ALPHA * e;
    }
    float m = fmaxf(fmaxf(ek[0], ek[1]), fmaxf(ek[2], ek[3]));
    #pragma unroll
    for (int o = 16; o; o >>= 1) m = fmaxf(m, __shfl_xor_sync(0xffffffffu, m, o));
    float s = 0.f;
    #pragma unroll
    for (int q = 0; q < 4; q++) {
        ek[q] = (q * 32 + lane < deg) ? __expf(ek[q] - m) : 0.f;
        s += ek[q];
    }
    #pragma unroll
    for (int o = 16; o; o >>= 1) s += __shfl_xor_sync(0xffffffffu, s, o);
    float inv = 1.f / s;

    float4 acc = {0.f, 0.f, 0.f, 0.f};
    const __half2* hb = g_h1h + (size_t)b * NN * 64;
    #pragma unroll
    for (int q = 0; q < 4; q++) {
        if (q * 32 >= deg) break;
        int kmax = deg - q * 32; if (kmax > 32) kmax = 32;
        #pragma unroll 4
        for (int l = 0; l < kmax; l++) {
            float wgt = __shfl_sync(0xffffffffu, ek[q], l);
            int   j   = __shfl_sync(0xffffffffu, nk[q], l);
            uint2 raw = *reinterpret_cast<const uint2*>(hb + (size_t)j * 64 + lane * 2);
            float2 fa = __half22float2(*reinterpret_cast<__half2*>(&raw.x));
            float2 fb = __half22float2(*reinterpret_cast<__half2*>(&raw.y));
            acc.x += wgt * fa.x; acc.y += wgt * fa.y;
            acc.z += wgt * fb.x; acc.w += wgt * fb.y;
        }
    }
    acc.x *= inv; acc.y *= inv; acc.z *= inv; acc.w *= inv;

    float4 gv;
    gv.x = 1.f / (1.f + __expf(-acc.x));
    gv.y = 1.f / (1.f + __expf(-acc.y));
    gv.z = 1.f / (1.f + __expf(-acc.z));
    gv.w = 1.f / (1.f + __expf(-acc.w));

    int idx = (b * NN + i) * 64;
    if (lane < 16) {     // cols 0..63 -> r: write r*state
        float4 st = *reinterpret_cast<const float4*>(state + idx + 4 * lane);
        float4 o = {gv.x * st.x, gv.y * st.y, gv.z * st.z, gv.w * st.w};
        *reinterpret_cast<float4*>(g_rs + idx + 4 * lane) = o;
    } else {             // cols 64..127 -> z
        *reinterpret_cast<float4*>(g_z + idx + 4 * lane - 64) = gv;
    }
}

// ---------------- K4: layer-2 attention + tanh + GRU blend ----------------
__global__ __launch_bounds__(128) void k_att2(const float* __restrict__ state,
                                              float* __restrict__ out) {
    int w = threadIdx.x >> 5, lane = threadIdx.x & 31;
    int i = blockIdx.x * 4 + w, b = blockIdx.y;
    int deg = g_cnt[i];
    float si = g_s2s[b * NN + i];

    float ek[4]; int nk[4];
    #pragma unroll
    for (int q = 0; q < 4; q++) {
        int k = q * 32 + lane;
        bool val = k < deg;
        int j = val ? g_nbr[i * MAXDEG + k] : 0;
        nk[q] = j;
        float e = val ? si + g_s2d[b * NN + j] : -3e38f;
        ek[q] = e > 0.f ? e : ALPHA * e;
    }
    float m = fmaxf(fmaxf(ek[0], ek[1]), fmaxf(ek[2], ek[3]));
    #pragma unroll
    for (int o = 16; o; o >>= 1) m = fmaxf(m, __shfl_xor_sync(0xffffffffu, m, o));
    float s = 0.f;
    #pragma unroll
    for (int q = 0; q < 4; q++) {
        ek[q] = (q * 32 + lane < deg) ? __expf(ek[q] - m) : 0.f;
        s += ek[q];
    }
    #pragma unroll
    for (int o = 16; o; o >>= 1) s += __shfl_xor_sync(0xffffffffu, s, o);
    float inv = 1.f / s;

    float2 acc = {0.f, 0.f};
    const __half2* hb = g_h2h + (size_t)b * NN * 32;
    #pragma unroll
    for (int q = 0; q < 4; q++) {
        if (q * 32 >= deg) break;
        int kmax = deg - q * 32; if (kmax > 32) kmax = 32;
        #pragma unroll 4
        for (int l = 0; l < kmax; l++) {
            float wgt = __shfl_sync(0xffffffffu, ek[q], l);
            int   j   = __shfl_sync(0xffffffffu, nk[q], l);
            unsigned raw = *reinterpret_cast<const unsigned*>(hb + (size_t)j * 32 + lane);
            float2 fa = __half22float2(*reinterpret_cast<__half2*>(&raw));
            acc.x += wgt * fa.x; acc.y += wgt * fa.y;
        }
    }
    acc.x *= inv; acc.y *= inv;

    int idx = (b * NN + i) * 64 + 2 * lane;
    float2 zz = *reinterpret_cast<const float2*>(g_z + idx);
    float2 st = *reinterpret_cast<const float2*>(state + idx);
    float2 o;
    o.x = zz.x * st.x + (1.f - zz.x) * tanhf(acc.x);
    o.y = zz.y * st.y + (1.f - zz.y) * tanhf(acc.y);
    *reinterpret_cast<float2*>(out + idx) = o;
}

// ---------------- launch ----------------
extern "C" void kernel_launch(void* const* d_in, const int* in_sizes, int n_in,
                              void* d_out, int out_size) {
    const float* X     = (const float*)d_in[0];
    const float* state = (const float*)d_in[1];
    const float* adj   = (const float*)d_in[2];
    const float* W1    = (const float*)d_in[3];
    const float* a1    = (const float*)d_in[4];
    const float* W2    = (const float*)d_in[5];
    const float* a2    = (const float*)d_in[6];
    float* out = (float*)d_out;

    const int SMEM_M1 = 128 * 136 * 2 + 128 * (128 + 8) * 2 + 2 * 128 * 4; // ~70.7 KB
    const int SMEM_M2 = 128 * 136 * 2 + 128 * (64 + 8) * 2 + 2 * 64 * 4;   // ~53.8 KB
    static int inited = 0;
    if (!inited) {
        cudaFuncSetAttribute(k_mma<128>, cudaFuncAttributeMaxDynamicSharedMemorySize, SMEM_M1);
        cudaFuncSetAttribute(k_mma<64>,  cudaFuncAttributeMaxDynamicSharedMemorySize, SMEM_M2);
        inited = 1;
    }

    k_build<<<NN, 256>>>(adj);

    dim3 gt(NN / 128, BB);          // 8 x 16 = 128 blocks
    k_mma<128><<<gt, 256, SMEM_M1>>>(X, state, W1, a1);

    dim3 ga(NN / 4, BB);            // warp per (b,i)
    k_att1<<<ga, 128>>>(state);

    k_mma<64><<<gt, 256, SMEM_M2>>>(X, state /*unused*/, W2, a2);

    k_att2<<<ga, 128>>>(state, out);
}

// round 8
// speedup vs baseline: 2.0733x; 1.0024x over previous
#include <cuda_runtime.h>
#include <cuda_fp16.h>
#include <cstdint>

#define BB 16
#define NN 1024
#define UU 64
#define MAXDEG 128
#define ALPHA 0.2f

// ---------------- scratch (device globals; no allocations) ----------------
__device__ int     g_cnt[NN];
__device__ int     g_nbr[NN * MAXDEG];
__device__ __half2 g_h1h[BB * NN * 64];   // h1 fp16, 128 cols = 64 half2
__device__ __half2 g_h2h[BB * NN * 32];   // h2 fp16, 64 cols = 32 half2
__device__ float   g_s1s[BB * NN];
__device__ float   g_s1d[BB * NN];
__device__ float   g_z  [BB * NN * UU];
__device__ float   g_rs [BB * NN * UU];   // r * state
__device__ float   g_s2s[BB * NN];
__device__ float   g_s2d[BB * NN];

__device__ __forceinline__ uint32_t smem_u32(const void* p) {
    uint32_t a;
    asm("{ .reg .u64 t; cvta.to.shared.u64 t, %1; cvt.u32.u64 %0, t; }" : "=r"(a) : "l"(p));
    return a;
}
__device__ __forceinline__ void ldm_x4(uint32_t& r0, uint32_t& r1, uint32_t& r2, uint32_t& r3,
                                       uint32_t addr) {
    asm volatile("ldmatrix.sync.aligned.m8n8.x4.shared.b16 {%0,%1,%2,%3}, [%4];"
                 : "=r"(r0), "=r"(r1), "=r"(r2), "=r"(r3) : "r"(addr));
}
__device__ __forceinline__ void ldm_x4t(uint32_t& r0, uint32_t& r1, uint32_t& r2, uint32_t& r3,
                                        uint32_t addr) {
    asm volatile("ldmatrix.sync.aligned.m8n8.x4.trans.shared.b16 {%0,%1,%2,%3}, [%4];"
                 : "=r"(r0), "=r"(r1), "=r"(r2), "=r"(r3) : "r"(addr));
}
__device__ __forceinline__ void mma16816(float* c, uint32_t a0, uint32_t a1, uint32_t a2,
                                         uint32_t a3, uint32_t b0, uint32_t b1) {
    asm volatile(
        "mma.sync.aligned.m16n8k16.row.col.f32.f16.f16.f32 "
        "{%0,%1,%2,%3}, {%4,%5,%6,%7}, {%8,%9}, {%0,%1,%2,%3};"
        : "+f"(c[0]), "+f"(c[1]), "+f"(c[2]), "+f"(c[3])
        : "r"(a0), "r"(a1), "r"(a2), "r"(a3), "r"(b0), "r"(b1));
}

// ---------------- K0: neighbor-list build via warp ballots ----------------
__global__ __launch_bounds__(256) void k_build(const float* __restrict__ adj) {
    int i = blockIdx.x, t = threadIdx.x, lane = t & 31, w = t >> 5;
    __shared__ int wtot[8];

    float4 v = *reinterpret_cast<const float4*>(adj + (size_t)i * NN + t * 4);
    unsigned f0 = v.x > 0.f, f1 = v.y > 0.f, f2 = v.z > 0.f, f3 = v.w > 0.f;
    unsigned m0 = __ballot_sync(~0u, f0), m1 = __ballot_sync(~0u, f1);
    unsigned m2 = __ballot_sync(~0u, f2), m3 = __ballot_sync(~0u, f3);
    unsigned lt = (1u << lane) - 1u;
    int pre = __popc(m0 & lt) + __popc(m1 & lt) + __popc(m2 & lt) + __popc(m3 & lt);
    if (lane == 0) wtot[w] = __popc(m0) + __popc(m1) + __popc(m2) + __popc(m3);
    __syncthreads();
    int base = 0;
    #pragma unroll
    for (int q = 0; q < 8; q++) base += (q < w) ? wtot[q] : 0;
    int p = base + pre;
    if (f0) { if (p < MAXDEG) g_nbr[i * MAXDEG + p] = t * 4 + 0; p++; }
    if (f1) { if (p < MAXDEG) g_nbr[i * MAXDEG + p] = t * 4 + 1; p++; }
    if (f2) { if (p < MAXDEG) g_nbr[i * MAXDEG + p] = t * 4 + 2; p++; }
    if (f3) { if (p < MAXDEG) g_nbr[i * MAXDEG + p] = t * 4 + 3; p++; }
    if (t == 255) {
        int tot = base + wtot[7];
        g_cnt[i] = tot < MAXDEG ? tot : MAXDEG;
    }
}

// ---------------- HMMA GEMM + scores (M=64 tiles, N split across warp halves) ----
// h[b,n,:] = fp16( concat(xa, xb)[b,n,:] @ W[128,FOUT] ),  ss/sd = h.a halves (fp32)
// Block: 256 thr / 8 warps; warps 0-3 = n-half 0, warps 4-7 = n-half 1; each warp m16.
template <int FOUT>
__global__ __launch_bounds__(256)
void k_mma(const float* __restrict__ xa, const float* __restrict__ xb_ext,
           const float* __restrict__ W, const float* __restrict__ a) {
    const float* xb = (FOUT == 128) ? xb_ext : g_rs;
    __half2* hh = (FOUT == 128) ? g_h1h : g_h2h;
    float* ss = (FOUT == 128) ? g_s1s : g_s2s;
    float* sd = (FOUT == 128) ? g_s1d : g_s2d;

    constexpr int AP = 136;         // padded halves/row (272B)
    constexpr int BP = FOUT + 8;    // padded halves/row
    constexpr int NTH = FOUT / 16;  // n8-tiles per warp half

    extern __shared__ char sm[];
    __half* As = (__half*)sm;                                 // [64][AP]
    __half* Bs = (__half*)(sm + 64 * AP * 2);                 // [128][BP]
    float*  sA = (float*)(sm + 64 * AP * 2 + 128 * BP * 2);   // [2*FOUT]
    float*  sred = sA + 2 * FOUT;                             // [2][64][2]

    int tid = threadIdx.x, w = tid >> 5, lane = tid & 31;
    int b = blockIdx.y;
    int row0 = blockIdx.x * 64;

    // ---- stage A: 64 rows x 128 cols of concat(xa,xb), fp32->fp16 ----
    #pragma unroll
    for (int it = 0; it < 4; it++) {
        int idx = it * 256 + tid;          // 1024 chunks of 8 halves
        int row = idx >> 4;
        int col0 = (idx & 15) * 8;
        const float* src = (col0 < 64)
            ? xa + ((size_t)b * NN + row0 + row) * 64 + col0
            : xb + ((size_t)b * NN + row0 + row) * 64 + (col0 - 64);
        float4 f0 = *reinterpret_cast<const float4*>(src);
        float4 f1 = *reinterpret_cast<const float4*>(src + 4);
        __half2 h0 = __floats2half2_rn(f0.x, f0.y);
        __half2 h1 = __floats2half2_rn(f0.z, f0.w);
        __half2 h2 = __floats2half2_rn(f1.x, f1.y);
        __half2 h3 = __floats2half2_rn(f1.z, f1.w);
        uint4 pk;
        pk.x = *reinterpret_cast<unsigned*>(&h0);
        pk.y = *reinterpret_cast<unsigned*>(&h1);
        pk.z = *reinterpret_cast<unsigned*>(&h2);
        pk.w = *reinterpret_cast<unsigned*>(&h3);
        *reinterpret_cast<uint4*>(As + row * AP + col0) = pk;
    }
    // ---- stage B = W: [128][FOUT] fp32 -> fp16 padded ----
    #pragma unroll
    for (int it = 0; it < FOUT / 16; it++) {
        int idx = it * 256 + tid;
        int k = idx / (FOUT / 8);
        int n0 = (idx - k * (FOUT / 8)) * 8;
        float4 f0 = *reinterpret_cast<const float4*>(W + (size_t)k * FOUT + n0);
        float4 f1 = *reinterpret_cast<const float4*>(W + (size_t)k * FOUT + n0 + 4);
        __half2 h0 = __floats2half2_rn(f0.x, f0.y);
        __half2 h1 = __floats2half2_rn(f0.z, f0.w);
        __half2 h2 = __floats2half2_rn(f1.x, f1.y);
        __half2 h3 = __floats2half2_rn(f1.z, f1.w);
        uint4 pk;
        pk.x = *reinterpret_cast<unsigned*>(&h0);
        pk.y = *reinterpret_cast<unsigned*>(&h1);
        pk.z = *reinterpret_cast<unsigned*>(&h2);
        pk.w = *reinterpret_cast<unsigned*>(&h3);
        *reinterpret_cast<uint4*>(Bs + k * BP + n0) = pk;
    }
    for (int c = tid; c < 2 * FOUT; c += 256) sA[c] = a[c];
    __syncthreads();

    // ---- mainloop: warp = (m16 slab mrow) x (n-half nh) ----
    int mrow = (w & 3) * 16, nh = w >> 2;
    float acc[NTH][4];
    #pragma unroll
    for (int j = 0; j < NTH; j++)
        #pragma unroll
        for (int q = 0; q < 4; q++) acc[j][q] = 0.f;

    uint32_t a_base = smem_u32(As + (mrow + (lane & 15)) * AP + ((lane >> 4) * 8));
    uint32_t b_base = smem_u32(Bs + (lane & 15) * BP + nh * (FOUT / 2) + ((lane >> 4) * 8));

    #pragma unroll
    for (int kk = 0; kk < 8; kk++) {
        uint32_t a0, a1, a2, a3;
        ldm_x4(a0, a1, a2, a3, a_base + kk * 32);
        #pragma unroll
        for (int j = 0; j < NTH / 2; j++) {
            uint32_t b0, b1, b2, b3;
            ldm_x4t(b0, b1, b2, b3, b_base + kk * (16 * BP * 2) + j * 32);
            mma16816(acc[2 * j],     a0, a1, a2, a3, b0, b1);
            mma16816(acc[2 * j + 1], a0, a1, a2, a3, b2, b3);
        }
    }

    // ---- epilogue ----
    int q = lane & 3, g = lane >> 2;
    int rowA = mrow + g, rowB = rowA + 8;
    size_t sbA = (size_t)b * NN + row0 + rowA;
    size_t sbB = (size_t)b * NN + row0 + rowB;
    __half2* hrA = hh + sbA * (FOUT / 2);
    __half2* hrB = hh + sbB * (FOUT / 2);

    float ps0 = 0.f, pd0 = 0.f, ps1 = 0.f, pd1 = 0.f;
    #pragma unroll
    for (int j = 0; j < NTH; j++) {
        int c = nh * (FOUT / 2) + j * 8 + 2 * q;
        ps0 += acc[j][0] * sA[c] + acc[j][1] * sA[c + 1];
        pd0 += acc[j][0] * sA[FOUT + c] + acc[j][1] * sA[FOUT + c + 1];
        ps1 += acc[j][2] * sA[c] + acc[j][3] * sA[c + 1];
        pd1 += acc[j][2] * sA[FOUT + c] + acc[j][3] * sA[FOUT + c + 1];
        hrA[c >> 1] = __floats2half2_rn(acc[j][0], acc[j][1]);
        hrB[c >> 1] = __floats2half2_rn(acc[j][2], acc[j][3]);
    }
    #pragma unroll
    for (int o = 1; o <= 2; o <<= 1) {
        ps0 += __shfl_xor_sync(0xffffffffu, ps0, o);
        pd0 += __shfl_xor_sync(0xffffffffu, pd0, o);
        ps1 += __shfl_xor_sync(0xffffffffu, ps1, o);
        pd1 += __shfl_xor_sync(0xffffffffu, pd1, o);
    }
    if (q == 0) {
        sred[(nh * 64 + rowA) * 2 + 0] = ps0;
        sred[(nh * 64 + rowA) * 2 + 1] = pd0;
        sred[(nh * 64 + rowB) * 2 + 0] = ps1;
        sred[(nh * 64 + rowB) * 2 + 1] = pd1;
    }
    __syncthreads();
    if (tid < 64) {
        size_t sb = (size_t)b * NN + row0 + tid;
        ss[sb] = sred[tid * 2]     + sred[(64 + tid) * 2];
        sd[sb] = sred[tid * 2 + 1] + sred[(64 + tid) * 2 + 1];
    }
}

// ---------------- K2: layer-1 attention + sigmoid gate (warp per (b,i)) ----
// Gather: 2 neighbor rows per warp iteration (half-warp x 16B).
__global__ __launch_bounds__(128) void k_att1(const float* __restrict__ state) {
    int w = threadIdx.x >> 5, lane = threadIdx.x & 31;
    int i = blockIdx.x * 4 + w, b = blockIdx.y;
    int deg = g_cnt[i];
    float si = g_s1s[b * NN + i];

    float ek[4]; int nk[4];
    #pragma unroll
    for (int q = 0; q < 4; q++) {
        int k = q * 32 + lane;
        bool val = k < deg;
        int j = val ? g_nbr[i * MAXDEG + k] : 0;
        nk[q] = j;
        float e = val ? si + g_s1d[b * NN + j] : -3e38f;
        ek[q] = e > 0.f ? e : ALPHA * e;
    }
    float m = fmaxf(fmaxf(ek[0], ek[1]), fmaxf(ek[2], ek[3]));
    #pragma unroll
    for (int o = 16; o; o >>= 1) m = fmaxf(m, __shfl_xor_sync(0xffffffffu, m, o));
    float s = 0.f;
    #pragma unroll
    for (int q = 0; q < 4; q++) {
        ek[q] = (q * 32 + lane < deg) ? __expf(ek[q] - m) : 0.f;
        s += ek[q];
    }
    #pragma unroll
    for (int o = 16; o; o >>= 1) s += __shfl_xor_sync(0xffffffffu, s, o);
    float inv = 1.f / s;

    int hf = lane >> 4, cl = lane & 15;    // row-parity, col-chunk (8 cols each)
    float acc[8];
    #pragma unroll
    for (int u = 0; u < 8; u++) acc[u] = 0.f;
    const __half2* hb = g_h1h + (size_t)b * NN * 64;
    #pragma unroll
    for (int q = 0; q < 4; q++) {
        if (q * 32 >= deg) break;
        int steps = deg - q * 32; if (steps > 32) steps = 32;
        int np = (steps + 1) >> 1;
        #pragma unroll 4
        for (int t = 0; t < np; t++) {
            int kl = 2 * t + hf;
            float wgt = __shfl_sync(0xffffffffu, ek[q], kl);
            int   j   = __shfl_sync(0xffffffffu, nk[q], kl);
            uint4 raw = *reinterpret_cast<const uint4*>(hb + (size_t)j * 64 + cl * 4);
            float2 f0 = __half22float2(*reinterpret_cast<__half2*>(&raw.x));
            float2 f1 = __half22float2(*reinterpret_cast<__half2*>(&raw.y));
            float2 f2 = __half22float2(*reinterpret_cast<__half2*>(&raw.z));
            float2 f3 = __half22float2(*reinterpret_cast<__half2*>(&raw.w));
            acc[0] += wgt * f0.x; acc[1] += wgt * f0.y;
            acc[2] += wgt * f1.x; acc[3] += wgt * f1.y;
            acc[4] += wgt * f2.x; acc[5] += wgt * f2.y;
            acc[6] += wgt * f3.x; acc[7] += wgt * f3.y;
        }
    }
    #pragma unroll
    for (int u = 0; u < 8; u++) acc[u] += __shfl_xor_sync(0xffffffffu, acc[u], 16);

    if (hf == 0) {   // lanes 0..15 hold final cols 8*cl .. 8*cl+7
        float gv[8];
        #pragma unroll
        for (int u = 0; u < 8; u++) gv[u] = 1.f / (1.f + __expf(-acc[u] * inv));
        int idx = (b * NN + i) * 64;
        if (cl < 8) {          // cols 0..63 -> r: write r*state
            int c0 = 8 * cl;
            float4 st0 = *reinterpret_cast<const float4*>(state + idx + c0);
            float4 st1 = *reinterpret_cast<const float4*>(state + idx + c0 + 4);
            float4 o0 = {gv[0] * st0.x, gv[1] * st0.y, gv[2] * st0.z, gv[3] * st0.w};
            float4 o1 = {gv[4] * st1.x, gv[5] * st1.y, gv[6] * st1.z, gv[7] * st1.w};
            *reinterpret_cast<float4*>(g_rs + idx + c0)     = o0;
            *reinterpret_cast<float4*>(g_rs + idx + c0 + 4) = o1;
        } else {               // cols 64..127 -> z
            int c0 = 8 * cl - 64;
            float4 o0 = {gv[0], gv[1], gv[2], gv[3]};
            float4 o1 = {gv[4], gv[5], gv[6], gv[7]};
            *reinterpret_cast<float4*>(g_z + idx + c0)     = o0;
            *reinterpret_cast<float4*>(g_z + idx + c0 + 4) = o1;
        }
    }
}

// ---------------- K4: layer-2 attention + tanh + GRU blend ----------------
// Gather: 4 neighbor rows per warp iteration (quarter-warp x 16B).
__global__ __launch_bounds__(128) void k_att2(const float* __restrict__ state,
                                              float* __restrict__ out) {
    int w = threadIdx.x >> 5, lane = threadIdx.x & 31;
    int i = blockIdx.x * 4 + w, b = blockIdx.y;
    int deg = g_cnt[i];
    float si = g_s2s[b * NN + i];

    float ek[4]; int nk[4];
    #pragma unroll
    for (int q = 0; q < 4; q++) {
        int k = q * 32 + lane;
        bool val = k < deg;
        int j = val ? g_nbr[i * MAXDEG + k] : 0;
        nk[q] = j;
        float e = val ? si + g_s2d[b * NN + j] : -3e38f;
        ek[q] = e > 0.f ? e : ALPHA * e;
    }
    float m = fmaxf(fmaxf(ek[0], ek[1]), fmaxf(ek[2], ek[3]));
    #pragma unroll
    for (int o = 16; o; o >>= 1) m = fmaxf(m, __shfl_xor_sync(0xffffffffu, m, o));
    float s = 0.f;
    #pragma unroll
    for (int q = 0; q < 4; q++) {
        ek[q] = (q * 32 + lane < deg) ? __expf(ek[q] - m) : 0.f;
        s += ek[q];
    }
    #pragma unroll
    for (int o = 16; o; o >>= 1) s += __shfl_xor_sync(0xffffffffu, s, o);
    float inv = 1.f / s;

    int hf = lane >> 3, cl = lane & 7;    // row-quarter, col-chunk (8 cols each)
    float acc[8];
    #pragma unroll
    for (int u = 0; u < 8; u++) acc[u] = 0.f;
    const __half2* hb = g_h2h + (size_t)b * NN * 32;
    #pragma unroll
    for (int q = 0; q < 4; q++) {
        if (q * 32 >= deg) break;
        int steps = deg - q * 32; if (steps > 32) steps = 32;
        int np = (steps + 3) >> 2;
        #pragma unroll 4
        for (int t = 0; t < np; t++) {
            int kl = 4 * t + hf;
            float wgt = __shfl_sync(0xffffffffu, ek[q], kl);
            int   j   = __shfl_sync(0xffffffffu, nk[q], kl);
            uint4 raw = *reinterpret_cast<const uint4*>(hb + (size_t)j * 32 + cl * 4);
            float2 f0 = __half22float2(*reinterpret_cast<__half2*>(&raw.x));
            float2 f1 = __half22float2(*reinterpret_cast<__half2*>(&raw.y));
            float2 f2 = __half22float2(*reinterpret_cast<__half2*>(&raw.z));
            float2 f3 = __half22float2(*reinterpret_cast<__half2*>(&raw.w));
            acc[0] += wgt * f0.x; acc[1] += wgt * f0.y;
            acc[2] += wgt * f1.x; acc[3] += wgt * f1.y;
            acc[4] += wgt * f2.x; acc[5] += wgt * f2.y;
            acc[6] += wgt * f3.x; acc[7] += wgt * f3.y;
        }
    }
    #pragma unroll
    for (int u = 0; u < 8; u++) {
        acc[u] += __shfl_xor_sync(0xffffffffu, acc[u], 8);
        acc[u] += __shfl_xor_sync(0xffffffffu, acc[u], 16);
    }

    if (lane < 8) {   // lanes 0..7 hold final cols 8*cl .. 8*cl+7
        int idx = (b * NN + i) * 64 + 8 * cl;
        float4 z0 = *reinterpret_cast<const float4*>(g_z + idx);
        float4 z1 = *reinterpret_cast<const float4*>(g_z + idx + 4);
        float4 s0 = *reinterpret_cast<const float4*>(state + idx);
        float4 s1 = *reinterpret_cast<const float4*>(state + idx + 4);
        float4 o0, o1;
        o0.x = z0.x * s0.x + (1.f - z0.x) * tanhf(acc[0] * inv);
        o0.y = z0.y * s0.y + (1.f - z0.y) * tanhf(acc[1] * inv);
        o0.z = z0.z * s0.z + (1.f - z0.z) * tanhf(acc[2] * inv);
        o0.w = z0.w * s0.w + (1.f - z0.w) * tanhf(acc[3] * inv);
        o1.x = z1.x * s1.x + (1.f - z1.x) * tanhf(acc[4] * inv);
        o1.y = z1.y * s1.y + (1.f - z1.y) * tanhf(acc[5] * inv);
        o1.z = z1.z * s1.z + (1.f - z1.z) * tanhf(acc[6] * inv);
        o1.w = z1.w * s1.w + (1.f - z1.w) * tanhf(acc[7] * inv);
        *reinterpret_cast<float4*>(out + idx)     = o0;
        *reinterpret_cast<float4*>(out + idx + 4) = o1;
    }
}

// ---------------- launch ----------------
extern "C" void kernel_launch(void* const* d_in, const int* in_sizes, int n_in,
                              void* d_out, int out_size) {
    const float* X     = (const float*)d_in[0];
    const float* state = (const float*)d_in[1];
    const float* adj   = (const float*)d_in[2];
    const float* W1    = (const float*)d_in[3];
    const float* a1    = (const float*)d_in[4];
    const float* W2    = (const float*)d_in[5];
    const float* a2    = (const float*)d_in[6];
    float* out = (float*)d_out;

    const int SMEM_M1 = 64 * 136 * 2 + 128 * 136 * 2 + 2 * 128 * 4 + 256 * 4; // 54272
    const int SMEM_M2 = 64 * 136 * 2 + 128 * 72 * 2  + 2 * 64 * 4  + 256 * 4; // 37376

    static int inited = 0;
    static cudaStream_t s_side = 0;
    static cudaEvent_t ev_fork = 0, ev_join = 0;
    if (!inited) {
        cudaFuncSetAttribute(k_mma<128>, cudaFuncAttributeMaxDynamicSharedMemorySize, SMEM_M1);
        cudaFuncSetAttribute(k_mma<64>,  cudaFuncAttributeMaxDynamicSharedMemorySize, SMEM_M2);
        cudaStreamCreateWithFlags(&s_side, cudaStreamNonBlocking);
        cudaEventCreateWithFlags(&ev_fork, cudaEventDisableTiming);
        cudaEventCreateWithFlags(&ev_join, cudaEventDisableTiming);
        inited = 1;
    }

    dim3 gt(NN / 64, BB);           // 16 x 16 = 256 blocks (2/SM)
    dim3 ga(NN / 4, BB);            // warp per (b,i)

    if (s_side) {
        // fork: adjacency build overlaps gemm1
        cudaEventRecord(ev_fork, 0);
        cudaStreamWaitEvent(s_side, ev_fork, 0);
        k_build<<<NN, 256, 0, s_side>>>(adj);
        cudaEventRecord(ev_join, s_side);

        k_mma<128><<<gt, 256, SMEM_M1>>>(X, state, W1, a1);
        cudaStreamWaitEvent(0, ev_join, 0);    // join before attention
    } else {
        k_build<<<NN, 256>>>(adj);
        k_mma<128><<<gt, 256, SMEM_M1>>>(X, state, W1, a1);
    }

    k_att1<<<ga, 128>>>(state);
    k_mma<64><<<gt, 256, SMEM_M2>>>(X, state /*unused*/, W2, a2);
    k_att2<<<ga, 128>>>(state, out);
}